// round 15
// baseline (speedup 1.0000x reference)
#include <cuda_runtime.h>
#include <cuda_bf16.h>
#include <cstdint>
#include <math.h>

#define BATCH 4096
#define PITCH 144            // bf16 tile row pitch (9 x 16B, ldsm conflict-free)

// ---------------- device scratch ------------------------------------------
__device__ __align__(16) float g_x[4096 * 192];
__device__ __align__(16) __nv_bfloat16 g_sh[4096 * 64],  g_sl[4096 * 64];
__device__ __align__(16) __nv_bfloat16 g_eh[100000 * 64], g_el[100000 * 64];
__device__ __align__(16) __nv_bfloat16 g_h0h[4096 * 512], g_h0l[4096 * 512];
__device__ __align__(16) __nv_bfloat16 g_h1h[4096 * 256], g_h1l[4096 * 256];
__device__ float g_h2[4096 * 128];
__device__ __align__(16) __nv_bfloat16 g_w0h[512 * 192], g_w0l[512 * 192];
__device__ __align__(16) __nv_bfloat16 g_w1h[256 * 512], g_w1l[256 * 512];
__device__ __align__(16) __nv_bfloat16 g_w2h[128 * 256], g_w2l[128 * 256];
__device__ __align__(16) __nv_bfloat16 g_lsh[64 * 3200], g_lsl[64 * 3200];
__device__ __align__(16) __nv_bfloat16 g_qh[4096 * 64],  g_ql[4096 * 64];

// ---------------- helpers --------------------------------------------------
__device__ __forceinline__ uint32_t smem_u32(const void* p) {
    uint32_t a;
    asm("{ .reg .u64 t; cvta.to.shared.u64 t, %1; cvt.u32.u64 %0, t; }" : "=r"(a) : "l"(p));
    return a;
}

__device__ __forceinline__ void split2(float a, float b, uint32_t& h, uint32_t& l) {
    __nv_bfloat162 hh = __floats2bfloat162_rn(a, b);
    float ra = a - __bfloat162float(hh.x);
    float rb = b - __bfloat162float(hh.y);
    __nv_bfloat162 ll = __floats2bfloat162_rn(ra, rb);
    h = *reinterpret_cast<uint32_t*>(&hh);
    l = *reinterpret_cast<uint32_t*>(&ll);
}

__device__ __forceinline__ void ldsm4(uint32_t* r, uint32_t addr) {
    asm volatile("ldmatrix.sync.aligned.m8n8.x4.shared.b16 {%0,%1,%2,%3}, [%4];"
                 : "=r"(r[0]), "=r"(r[1]), "=r"(r[2]), "=r"(r[3]) : "r"(addr));
}

__device__ __forceinline__ void mma16816(float* c, const uint32_t* a, const uint32_t* b) {
    asm volatile(
        "mma.sync.aligned.m16n8k16.row.col.f32.bf16.bf16.f32 "
        "{%0,%1,%2,%3}, {%4,%5,%6,%7}, {%8,%9}, {%0,%1,%2,%3};"
        : "+f"(c[0]), "+f"(c[1]), "+f"(c[2]), "+f"(c[3])
        : "r"(a[0]), "r"(a[1]), "r"(a[2]), "r"(a[3]), "r"(b[0]), "r"(b[1]));
}

// warp computes its 16 x (NT*8) C tile for one K=64 stage (3-product split)
template<int NT>
__device__ __forceinline__ void warp_compute(uint32_t aH, uint32_t aL,
                                             uint32_t bH, uint32_t bL,
                                             int lane, int wrow, float (*acc)[4]) {
    #pragma unroll
    for (int ks = 0; ks < 4; ks++) {
        const int k0 = ks * 16;
        uint32_t aAddr = aH + (wrow + (lane & 15)) * PITCH + (k0 + ((lane >> 4) & 1) * 8) * 2;
        uint32_t ah[4], al[4];
        ldsm4(ah, aAddr);
        ldsm4(al, aAddr + (aL - aH));
        #pragma unroll
        for (int np = 0; np < NT / 2; np++) {
            uint32_t bAddr = bH + (np * 16 + ((lane >> 4) & 1) * 8 + (lane & 7)) * PITCH
                           + (k0 + ((lane >> 3) & 1) * 8) * 2;
            uint32_t bh[4], bl[4];
            ldsm4(bh, bAddr);
            ldsm4(bl, bAddr + (bL - bH));
            mma16816(acc[np * 2],     ah, bh);
            mma16816(acc[np * 2],     ah, bl);
            mma16816(acc[np * 2],     al, bh);
            mma16816(acc[np * 2 + 1], ah, bh + 2);
            mma16816(acc[np * 2 + 1], ah, bl + 2);
            mma16816(acc[np * 2 + 1], al, bh + 2);
        }
    }
}

// ---------------------------------------------------------------------------
// fused gather + operand prep. grid 11826 (see dispatch below)
// ---------------------------------------------------------------------------
__device__ __forceinline__ void wsplit(const float* W, __nv_bfloat16* th,
                                       __nv_bfloat16* tl, int K, int N, int o) {
    int n = o / K, k = o % K;
    float v = W[k * N + n];
    __nv_bfloat16 h = __float2bfloat16_rn(v);
    th[o] = h;
    tl[o] = __float2bfloat16_rn(v - __bfloat162float(h));
}

__device__ __forceinline__ void vsplit4(const float* __restrict__ src,
                                        __nv_bfloat16* __restrict__ th,
                                        __nv_bfloat16* __restrict__ tl, long o4) {
    float4 v = *reinterpret_cast<const float4*>(&src[o4 * 4]);
    uint32_t h0, l0, h1, l1;
    split2(v.x, v.y, h0, l0);
    split2(v.z, v.w, h1, l1);
    *reinterpret_cast<uint2*>(&th[o4 * 4]) = make_uint2(h0, h1);
    *reinterpret_cast<uint2*>(&tl[o4 * 4]) = make_uint2(l0, l1);
}

__global__ void prep_gather(const float* __restrict__ fv,
                            const int* __restrict__ idx,
                            const float* __restrict__ emb,
                            const float* __restrict__ theta,
                            const float* __restrict__ W0, const float* __restrict__ W1,
                            const float* __restrict__ W2, const float* __restrict__ LS,
                            const float* __restrict__ quad)
{
    const int blk = blockIdx.x;
    const int t = threadIdx.x;
    if (blk >= 4096) {
        const int b = blk - 4096;
        if (b < 384)       wsplit(W0, g_w0h, g_w0l, 192, 512, b * 256 + t);
        else if (b < 896)  wsplit(W1, g_w1h, g_w1l, 512, 256, (b - 384) * 256 + t);
        else if (b < 1024) wsplit(W2, g_w2h, g_w2l, 256, 128, (b - 896) * 256 + t);
        else if (b < 1224) vsplit4(LS,   g_lsh, g_lsl, (long)(b - 1024) * 256 + t);
        else if (b < 1480) vsplit4(quad, g_qh,  g_ql,  (long)(b - 1224) * 256 + t);
        else               vsplit4(emb,  g_eh,  g_el,  (long)(b - 1480) * 256 + t);
        return;
    }

    const int b = blk;
    __shared__ float feats[50 * 65];
    __shared__ float sq[50];
    __shared__ int   sidx[50];
    __shared__ float sfv[50];

    if (t < 50) { sidx[t] = idx[b * 50 + t]; sfv[t] = fv[b * 50 + t]; }
    __syncthreads();
    for (int j = t; j < 800; j += 256) {          // float4-vectorized gather
        int n = j >> 4, m4 = (j & 15) * 4;
        float4 e = *reinterpret_cast<const float4*>(&emb[(long)sidx[n] * 64 + m4]);
        float s = sfv[n];
        feats[n * 65 + m4]     = e.x * s;
        feats[n * 65 + m4 + 1] = e.y * s;
        feats[n * 65 + m4 + 2] = e.z * s;
        feats[n * 65 + m4 + 3] = e.w * s;
    }
    __syncthreads();
    if (t < 64) {   // s + exact bf16 split
        float acc = 0.f;
        #pragma unroll
        for (int n = 0; n < 50; n++) acc += feats[n * 65 + t];
        __nv_bfloat16 h = __float2bfloat16_rn(acc);
        g_sh[b * 64 + t] = h;
        g_sl[b * 64 + t] = __float2bfloat16_rn(acc - __bfloat162float(h));
        g_x[b * 192 + t] = 0.f;   // zero l_z accumulation slot
    }
    if (t >= 64 && t < 114) {
        int n = t - 64;
        float acc = 0.f;
        #pragma unroll
        for (int m = 0; m < 64; m++) { float v = feats[n * 65 + m]; acc += v * v; }
        sq[n] = acc;
    }
    __syncthreads();
    if (t < 64) {   // l_p_in
        float acc = 0.f;
        #pragma unroll
        for (int n = 0; n < 50; n++) { float th = theta[t * 50 + n]; acc += th * th * sq[n]; }
        g_x[b * 192 + 64 + t] = acc;
    }
}

// ============ tile layout ===================================================
#define T_AL  18432          // A-lo offset (A tile 128 rows x 144B)
#define T_BH  36864          // B-hi offset
#define T_BL64 46080         // B-lo offset for 64-row B
#define BUF64 55296          // A(hi,lo) + 64-row B(hi,lo)

// ---------------------------------------------------------------------------
// l_z: C[b,d] += sum_n fv[b,n] * (emb[idx[b,n]] . LS[d,n,:]).
// idx/fv read straight from gmem (L1 broadcast), no smem preload ->
// smem = 2*BUF64 = 110592 -> 2 blocks/SM. grid (32 row-tiles, 8 k-splits).
// ---------------------------------------------------------------------------
__global__ void __launch_bounds__(256) lz_mma(const float* __restrict__ fv,
                                              const int* __restrict__ idx)
{
    extern __shared__ char sm[];
    const int tid = threadIdx.x, wid = tid >> 5, lane = tid & 31;
    const uint32_t sb = smem_u32(sm);
    const int rowBase = blockIdx.x * 128;
    const int y = blockIdx.y;
    const int start = y * 6 + min(y, 2);
    const int count = (y < 2) ? 7 : 6;
    const int wrow = wid * 16;

    float acc[8][4];
    #pragma unroll
    for (int i = 0; i < 8; i++)
        #pragma unroll
        for (int j = 0; j < 4; j++) acc[i][j] = 0.f;

    auto stage = [&](int buf, int ci) {
        char* base = sm + buf * BUF64;
        const int n = start + ci;
        #pragma unroll
        for (int p = 0; p < 4; p++) {            // A hi/lo: gather 128 emb rows
            int j = tid + p * 256;
            int r = j >> 3, q = j & 7;
            long eo = (long)idx[(rowBase + r) * 50 + n] * 64 + q * 8;
            *reinterpret_cast<uint4*>(base + r * PITCH + q * 16) =
                *reinterpret_cast<const uint4*>(&g_eh[eo]);
            *reinterpret_cast<uint4*>(base + T_AL + r * PITCH + q * 16) =
                *reinterpret_cast<const uint4*>(&g_el[eo]);
        }
        #pragma unroll
        for (int p = 0; p < 2; p++) {            // B hi/lo: LS copy
            int j = tid + p * 256;
            int d = j >> 3, q = j & 7;
            long off = (long)d * 3200 + n * 64 + q * 8;
            *reinterpret_cast<uint4*>(base + T_BH + d * PITCH + q * 16) =
                *reinterpret_cast<const uint4*>(&g_lsh[off]);
            *reinterpret_cast<uint4*>(base + T_BL64 + d * PITCH + q * 16) =
                *reinterpret_cast<const uint4*>(&g_lsl[off]);
        }
    };

    const int lr = wrow + (lane >> 2);           // local row of acc[..][0,1]
    stage(0, 0);
    __syncthreads();
    for (int ci = 0; ci < count; ci++) {
        if (ci + 1 < count) stage((ci + 1) & 1, ci + 1);
        uint32_t cb = sb + (ci & 1) * BUF64;
        float cs[8][4];
        #pragma unroll
        for (int i = 0; i < 8; i++)
            #pragma unroll
            for (int j = 0; j < 4; j++) cs[i][j] = 0.f;
        warp_compute<8>(cb, cb + T_AL, cb + T_BH, cb + T_BL64, lane, wrow, cs);
        const int n = start + ci;
        const float fa = fv[(rowBase + lr) * 50 + n];
        const float fb = fv[(rowBase + lr + 8) * 50 + n];
        #pragma unroll
        for (int nt = 0; nt < 8; nt++) {
            acc[nt][0] += fa * cs[nt][0];
            acc[nt][1] += fa * cs[nt][1];
            acc[nt][2] += fb * cs[nt][2];
            acc[nt][3] += fb * cs[nt][3];
        }
        __syncthreads();
    }

    const int row0 = rowBase + lr;
    #pragma unroll
    for (int nt = 0; nt < 8; nt++) {
        const int col = nt * 8 + (lane & 3) * 2;
        atomicAdd(&g_x[row0 * 192 + col],           acc[nt][0]);
        atomicAdd(&g_x[row0 * 192 + col + 1],       acc[nt][1]);
        atomicAdd(&g_x[(row0 + 8) * 192 + col],     acc[nt][2]);
        atomicAdd(&g_x[(row0 + 8) * 192 + col + 1], acc[nt][3]);
    }
}

// ---------------------------------------------------------------------------
// l_p_out via T-GEMM: T[b, d*64+m] = sum_n s[b,n]*quad[d,m,n] (quad flat
// [4096,64] IS the K-major B), epilogue contracts sum_m s[b,m]*T.
// ONE K-stage, pure copies, no atomics. grid (32, 32). 73728 B smem.
// ---------------------------------------------------------------------------
__global__ void __launch_bounds__(256) opnn_mma()
{
    extern __shared__ char sm[];
    const int tid = threadIdx.x, wid = tid >> 5, lane = tid & 31;
    const uint32_t sb = smem_u32(sm);
    const int rowBase = blockIdx.x * 128;
    const int colBase = blockIdx.y * 128;
    const int wrow = wid * 16;

    #pragma unroll
    for (int p = 0; p < 4; p++) {                // A hi/lo from s split
        int j = tid + p * 256;
        int r = j >> 3, q = j & 7;
        long off = (long)(rowBase + r) * 64 + q * 8;
        *reinterpret_cast<uint4*>(sm + r * PITCH + q * 16) =
            *reinterpret_cast<const uint4*>(&g_sh[off]);
        *reinterpret_cast<uint4*>(sm + T_AL + r * PITCH + q * 16) =
            *reinterpret_cast<const uint4*>(&g_sl[off]);
    }
    #pragma unroll
    for (int p = 0; p < 4; p++) {                // B hi/lo from quad split
        int j = tid + p * 256;
        int d = j >> 3, q = j & 7;
        long off = (long)(colBase + d) * 64 + q * 8;
        *reinterpret_cast<uint4*>(sm + T_BH + d * PITCH + q * 16) =
            *reinterpret_cast<const uint4*>(&g_qh[off]);
        *reinterpret_cast<uint4*>(sm + 55296 + d * PITCH + q * 16) =
            *reinterpret_cast<const uint4*>(&g_ql[off]);
    }
    __syncthreads();

    float acc[16][4];
    #pragma unroll
    for (int i = 0; i < 16; i++)
        #pragma unroll
        for (int j = 0; j < 4; j++) acc[i][j] = 0.f;

    warp_compute<16>(sb, sb + T_AL, sb + T_BH, sb + 55296, lane, wrow, acc);

    const int lr0 = wrow + (lane >> 2);
    float part[4] = {0.f, 0.f, 0.f, 0.f};
    #pragma unroll
    for (int h = 0; h < 2; h++) {
        #pragma unroll
        for (int nt = 0; nt < 8; nt++) {
            const int a = h * 8 + nt;
            const int m = nt * 8 + (lane & 3) * 2;
            __nv_bfloat162 h0 = *reinterpret_cast<__nv_bfloat162*>(sm + lr0 * PITCH + m * 2);
            __nv_bfloat162 l0 = *reinterpret_cast<__nv_bfloat162*>(sm + T_AL + lr0 * PITCH + m * 2);
            __nv_bfloat162 h1 = *reinterpret_cast<__nv_bfloat162*>(sm + (lr0 + 8) * PITCH + m * 2);
            __nv_bfloat162 l1 = *reinterpret_cast<__nv_bfloat162*>(sm + T_AL + (lr0 + 8) * PITCH + m * 2);
            part[h * 2]     += acc[a][0] * (__bfloat162float(h0.x) + __bfloat162float(l0.x))
                             + acc[a][1] * (__bfloat162float(h0.y) + __bfloat162float(l0.y));
            part[h * 2 + 1] += acc[a][2] * (__bfloat162float(h1.x) + __bfloat162float(l1.x))
                             + acc[a][3] * (__bfloat162float(h1.y) + __bfloat162float(l1.y));
        }
    }
    #pragma unroll
    for (int i = 0; i < 4; i++) {
        part[i] += __shfl_xor_sync(0xffffffffu, part[i], 1);
        part[i] += __shfl_xor_sync(0xffffffffu, part[i], 2);
    }
    if ((lane & 3) == 0) {
        const int d0 = colBase >> 6;
        g_x[(rowBase + lr0) * 192 + 128 + d0]         = part[0];
        g_x[(rowBase + lr0) * 192 + 128 + d0 + 1]     = part[2];
        g_x[(rowBase + lr0 + 8) * 192 + 128 + d0]     = part[1];
        g_x[(rowBase + lr0 + 8) * 192 + 128 + d0 + 1] = part[3];
    }
}

// ---------------------------------------------------------------------------
// MLP layer: C = A @ W^T + BN + ReLU. NT n-tiles; AF32=1 stages A from fp32
// (g_x) with on-the-fly split (overlapped with MMA via double buffering).
// ---------------------------------------------------------------------------
template<int NT, int OUT_SPLIT, int AF32>
__global__ void __launch_bounds__(256) mlp_mma(
    const float* __restrict__ af,
    const __nv_bfloat16* __restrict__ ah, const __nv_bfloat16* __restrict__ al,
    const __nv_bfloat16* __restrict__ wh, const __nv_bfloat16* __restrict__ wl,
    __nv_bfloat16* __restrict__ oh, __nv_bfloat16* __restrict__ ol,
    float* __restrict__ of, int K, int N,
    const float* __restrict__ bias, const float* __restrict__ gam,
    const float* __restrict__ bet, const float* __restrict__ mu,
    const float* __restrict__ var)
{
    constexpr int BROWS = NT * 8;
    constexpr int BB    = BROWS * PITCH;
    constexpr int OBH   = 36864;
    constexpr int OBL   = 36864 + BB;
    constexpr int BUFSZ = 36864 + 2 * BB;

    extern __shared__ char sm[];
    const int tid = threadIdx.x, wid = tid >> 5, lane = tid & 31;
    const uint32_t sb = smem_u32(sm);
    float* sscale = reinterpret_cast<float*>(sm + 2 * BUFSZ);
    float* sshift = sscale + BROWS;
    const int rowBase = blockIdx.y * 128;
    const int colBase = blockIdx.x * BROWS;
    const int wrow = wid * 16;

    if (tid < BROWS) {
        int c = colBase + tid;
        float sc = gam[c] * rsqrtf(var[c] + 1e-3f);
        sscale[tid] = sc;
        sshift[tid] = (bias[c] - mu[c]) * sc + bet[c];
    }

    float acc[NT][4];
    #pragma unroll
    for (int i = 0; i < NT; i++)
        #pragma unroll
        for (int j = 0; j < 4; j++) acc[i][j] = 0.f;

    const int nch = K >> 6;
    auto stage = [&](int buf, int ch) {
        char* base = sm + buf * BUFSZ;
        const int k0 = ch * 64;
        #pragma unroll
        for (int p = 0; p < 4; p++) {
            int j = tid + p * 256;
            int r = j >> 3, q = j & 7;
            if (AF32) {
                long off = (long)(rowBase + r) * K + k0 + q * 8;
                float4 v0 = *reinterpret_cast<const float4*>(&af[off]);
                float4 v1 = *reinterpret_cast<const float4*>(&af[off + 4]);
                uint32_t h0, l0, h1, l1, h2, l2, h3, l3;
                split2(v0.x, v0.y, h0, l0);
                split2(v0.z, v0.w, h1, l1);
                split2(v1.x, v1.y, h2, l2);
                split2(v1.z, v1.w, h3, l3);
                *reinterpret_cast<uint4*>(base + r * PITCH + q * 16) =
                    make_uint4(h0, h1, h2, h3);
                *reinterpret_cast<uint4*>(base + T_AL + r * PITCH + q * 16) =
                    make_uint4(l0, l1, l2, l3);
            } else {
                long off = (long)(rowBase + r) * K + k0 + q * 8;
                *reinterpret_cast<uint4*>(base + r * PITCH + q * 16) =
                    *reinterpret_cast<const uint4*>(&ah[off]);
                *reinterpret_cast<uint4*>(base + T_AL + r * PITCH + q * 16) =
                    *reinterpret_cast<const uint4*>(&al[off]);
            }
        }
        #pragma unroll
        for (int p = 0; p < NT / 4; p++) {
            int j = tid + p * 256;
            int d = j >> 3, q = j & 7;
            long off = (long)(colBase + d) * K + k0 + q * 8;
            *reinterpret_cast<uint4*>(base + OBH + d * PITCH + q * 16) =
                *reinterpret_cast<const uint4*>(&wh[off]);
            *reinterpret_cast<uint4*>(base + OBL + d * PITCH + q * 16) =
                *reinterpret_cast<const uint4*>(&wl[off]);
        }
    };

    stage(0, 0);
    __syncthreads();
    for (int ch = 0; ch < nch; ch++) {
        if (ch + 1 < nch) stage((ch + 1) & 1, ch + 1);
        uint32_t cb = sb + (ch & 1) * BUFSZ;
        warp_compute<NT>(cb, cb + T_AL, cb + OBH, cb + OBL, lane, wrow, acc);
        __syncthreads();
    }

    const int row0 = rowBase + wrow + (lane >> 2);
    #pragma unroll
    for (int nt = 0; nt < NT; nt++) {
        const int cl = nt * 8 + (lane & 3) * 2;
        const float s0 = sscale[cl], s1 = sscale[cl + 1];
        const float t0 = sshift[cl], t1 = sshift[cl + 1];
        float v0 = fmaxf(acc[nt][0] * s0 + t0, 0.f);
        float v1 = fmaxf(acc[nt][1] * s1 + t1, 0.f);
        float v2 = fmaxf(acc[nt][2] * s0 + t0, 0.f);
        float v3 = fmaxf(acc[nt][3] * s1 + t1, 0.f);
        if (OUT_SPLIT) {
            uint32_t h, l;
            split2(v0, v1, h, l);
            *reinterpret_cast<uint32_t*>(&oh[(long)row0 * N + colBase + cl]) = h;
            *reinterpret_cast<uint32_t*>(&ol[(long)row0 * N + colBase + cl]) = l;
            split2(v2, v3, h, l);
            *reinterpret_cast<uint32_t*>(&oh[(long)(row0 + 8) * N + colBase + cl]) = h;
            *reinterpret_cast<uint32_t*>(&ol[(long)(row0 + 8) * N + colBase + cl]) = l;
        } else {
            *reinterpret_cast<float2*>(&of[(long)row0 * N + colBase + cl]) = make_float2(v0, v1);
            *reinterpret_cast<float2*>(&of[(long)(row0 + 8) * N + colBase + cl]) = make_float2(v2, v3);
        }
    }
}

// ---------------------------------------------------------------------------
// final dense [4096,128]@[128,1] + sigmoid
// ---------------------------------------------------------------------------
__global__ void final_kernel(const float* __restrict__ Wout,
                             const float* __restrict__ bout,
                             float* __restrict__ out)
{
    const int warp = (blockIdx.x * blockDim.x + threadIdx.x) >> 5;
    const int lane = threadIdx.x & 31;
    if (warp >= BATCH) return;
    const float* h = &g_h2[warp * 128];
    float acc = h[lane]      * Wout[lane]
              + h[lane + 32] * Wout[lane + 32]
              + h[lane + 64] * Wout[lane + 64]
              + h[lane + 96] * Wout[lane + 96];
    #pragma unroll
    for (int off = 16; off > 0; off >>= 1)
        acc += __shfl_down_sync(0xffffffffu, acc, off);
    if (lane == 0) {
        float z = acc + bout[0];
        out[warp] = 1.f / (1.f + expf(-z));
    }
}

// ---------------------------------------------------------------------------
extern "C" void kernel_launch(void* const* d_in, const int* in_sizes, int n_in,
                              void* d_out, int out_size)
{
    const float* fv    = (const float*)d_in[0];
    const int*   idx   = (const int*)  d_in[1];
    const float* emb   = (const float*)d_in[2];
    const float* LS    = (const float*)d_in[3];
    const float* theta = (const float*)d_in[4];
    const float* quad  = (const float*)d_in[5];
    const float* W0  = (const float*)d_in[6];
    const float* b0  = (const float*)d_in[7];
    const float* gm0 = (const float*)d_in[8];
    const float* be0 = (const float*)d_in[9];
    const float* m0  = (const float*)d_in[10];
    const float* v0  = (const float*)d_in[11];
    const float* W1  = (const float*)d_in[12];
    const float* b1  = (const float*)d_in[13];
    const float* gm1 = (const float*)d_in[14];
    const float* be1 = (const float*)d_in[15];
    const float* m1  = (const float*)d_in[16];
    const float* v1  = (const float*)d_in[17];
    const float* W2  = (const float*)d_in[18];
    const float* b2  = (const float*)d_in[19];
    const float* gm2 = (const float*)d_in[20];
    const float* be2 = (const float*)d_in[21];
    const float* m2  = (const float*)d_in[22];
    const float* v2  = (const float*)d_in[23];
    const float* Wout = (const float*)d_in[24];
    const float* bout = (const float*)d_in[25];
    float* out = (float*)d_out;

    float *p_x, *p_h2;
    __nv_bfloat16 *p_h0h, *p_h0l, *p_h1h, *p_h1l;
    __nv_bfloat16 *p_w0h, *p_w0l, *p_w1h, *p_w1l, *p_w2h, *p_w2l;
    cudaGetSymbolAddress((void**)&p_x,   g_x);
    cudaGetSymbolAddress((void**)&p_h0h, g_h0h);
    cudaGetSymbolAddress((void**)&p_h0l, g_h0l);
    cudaGetSymbolAddress((void**)&p_h1h, g_h1h);
    cudaGetSymbolAddress((void**)&p_h1l, g_h1l);
    cudaGetSymbolAddress((void**)&p_h2,  g_h2);
    cudaGetSymbolAddress((void**)&p_w0h, g_w0h);
    cudaGetSymbolAddress((void**)&p_w0l, g_w0l);
    cudaGetSymbolAddress((void**)&p_w1h, g_w1h);
    cudaGetSymbolAddress((void**)&p_w1l, g_w1l);
    cudaGetSymbolAddress((void**)&p_w2h, g_w2h);
    cudaGetSymbolAddress((void**)&p_w2l, g_w2l);

    const int SMEM_LZ    = 2 * BUF64;                                  // 110592 -> 2/SM
    const int SMEM_OP    = 73728;
    const int SMEM_MLP16 = 2 * (36864 + 2 * 128 * PITCH) + 1024;       // 148480
    const int SMEM_MLP8  = 2 * BUF64 + 1024;                           // 111616
    const int SMEM_MLP4  = 2 * (36864 + 2 * 32 * PITCH) + 1024;        // 93184
    cudaFuncSetAttribute(lz_mma,          cudaFuncAttributeMaxDynamicSharedMemorySize, SMEM_LZ);
    cudaFuncSetAttribute(opnn_mma,        cudaFuncAttributeMaxDynamicSharedMemorySize, SMEM_OP);
    cudaFuncSetAttribute(mlp_mma<16,1,1>, cudaFuncAttributeMaxDynamicSharedMemorySize, SMEM_MLP16);
    cudaFuncSetAttribute(mlp_mma<8,1,0>,  cudaFuncAttributeMaxDynamicSharedMemorySize, SMEM_MLP8);
    cudaFuncSetAttribute(mlp_mma<4,0,0>,  cudaFuncAttributeMaxDynamicSharedMemorySize, SMEM_MLP4);

    // 1) fused gather + operand prep (incl. emb table split)
    prep_gather<<<11826, 256>>>(fv, idx, emb, theta, W0, W1, W2, LS, quad);
    // 2) l_z (copy-only gather staging, fv in epilogue, 2 blocks/SM)
    lz_mma<<<dim3(32, 8), 256, SMEM_LZ>>>(fv, idx);
    // 3) l_p_out (single-K-stage T-GEMM + in-register contraction)
    opnn_mma<<<dim3(32, 32), 256, SMEM_OP>>>();
    // 4) MLP (layer 0 splits fp32 x on the fly — no convert kernel)
    mlp_mma<16,1,1><<<dim3(4, 32), 256, SMEM_MLP16>>>(p_x, nullptr, nullptr,
        p_w0h, p_w0l, p_h0h, p_h0l, nullptr, 192, 512, b0, gm0, be0, m0, v0);
    mlp_mma<8,1,0><<<dim3(4, 32), 256, SMEM_MLP8>>>(nullptr, p_h0h, p_h0l,
        p_w1h, p_w1l, p_h1h, p_h1l, nullptr, 512, 256, b1, gm1, be1, m1, v1);
    mlp_mma<4,0,0><<<dim3(4, 32), 256, SMEM_MLP4>>>(nullptr, p_h1h, p_h1l,
        p_w2h, p_w2l, nullptr, nullptr, p_h2, 256, 128, b2, gm2, be2, m2, v2);
    // 5) output + sigmoid
    final_kernel<<<BATCH * 32 / 256, 256>>>(Wout, bout, out);
}

// round 16
// speedup vs baseline: 1.0348x; 1.0348x over previous
#include <cuda_runtime.h>
#include <cuda_bf16.h>
#include <cstdint>
#include <math.h>

#define BATCH 4096
#define PITCH 144            // bf16 tile row pitch (9 x 16B, ldsm conflict-free)

// ---------------- device scratch ------------------------------------------
__device__ __align__(16) float g_x[4096 * 192];
__device__ __align__(16) __nv_bfloat16 g_sh[4096 * 64],  g_sl[4096 * 64];
__device__ __align__(16) __nv_bfloat16 g_h0h[4096 * 512], g_h0l[4096 * 512];
__device__ __align__(16) __nv_bfloat16 g_h1h[4096 * 256], g_h1l[4096 * 256];
__device__ float g_h2[4096 * 128];
__device__ __align__(16) __nv_bfloat16 g_w0h[512 * 192], g_w0l[512 * 192];
__device__ __align__(16) __nv_bfloat16 g_w1h[256 * 512], g_w1l[256 * 512];
__device__ __align__(16) __nv_bfloat16 g_w2h[128 * 256], g_w2l[128 * 256];
__device__ __align__(16) __nv_bfloat16 g_lsh[64 * 3200], g_lsl[64 * 3200];
__device__ __align__(16) __nv_bfloat16 g_qh[4096 * 64],  g_ql[4096 * 64];

// ---------------- helpers --------------------------------------------------
__device__ __forceinline__ uint32_t smem_u32(const void* p) {
    uint32_t a;
    asm("{ .reg .u64 t; cvta.to.shared.u64 t, %1; cvt.u32.u64 %0, t; }" : "=r"(a) : "l"(p));
    return a;
}

__device__ __forceinline__ void split2(float a, float b, uint32_t& h, uint32_t& l) {
    __nv_bfloat162 hh = __floats2bfloat162_rn(a, b);
    float ra = a - __bfloat162float(hh.x);
    float rb = b - __bfloat162float(hh.y);
    __nv_bfloat162 ll = __floats2bfloat162_rn(ra, rb);
    h = *reinterpret_cast<uint32_t*>(&hh);
    l = *reinterpret_cast<uint32_t*>(&ll);
}

__device__ __forceinline__ void ldsm4(uint32_t* r, uint32_t addr) {
    asm volatile("ldmatrix.sync.aligned.m8n8.x4.shared.b16 {%0,%1,%2,%3}, [%4];"
                 : "=r"(r[0]), "=r"(r[1]), "=r"(r[2]), "=r"(r[3]) : "r"(addr));
}

__device__ __forceinline__ void mma16816(float* c, const uint32_t* a, const uint32_t* b) {
    asm volatile(
        "mma.sync.aligned.m16n8k16.row.col.f32.bf16.bf16.f32 "
        "{%0,%1,%2,%3}, {%4,%5,%6,%7}, {%8,%9}, {%0,%1,%2,%3};"
        : "+f"(c[0]), "+f"(c[1]), "+f"(c[2]), "+f"(c[3])
        : "r"(a[0]), "r"(a[1]), "r"(a[2]), "r"(a[3]), "r"(b[0]), "r"(b[1]));
}

// warp computes its 16 x (NT*8) C tile for one K=64 stage (3-product split)
template<int NT>
__device__ __forceinline__ void warp_compute(uint32_t aH, uint32_t aL,
                                             uint32_t bH, uint32_t bL,
                                             int lane, int wrow, float (*acc)[4]) {
    #pragma unroll
    for (int ks = 0; ks < 4; ks++) {
        const int k0 = ks * 16;
        uint32_t aAddr = aH + (wrow + (lane & 15)) * PITCH + (k0 + ((lane >> 4) & 1) * 8) * 2;
        uint32_t ah[4], al[4];
        ldsm4(ah, aAddr);
        ldsm4(al, aAddr + (aL - aH));
        #pragma unroll
        for (int np = 0; np < NT / 2; np++) {
            uint32_t bAddr = bH + (np * 16 + ((lane >> 4) & 1) * 8 + (lane & 7)) * PITCH
                           + (k0 + ((lane >> 3) & 1) * 8) * 2;
            uint32_t bh[4], bl[4];
            ldsm4(bh, bAddr);
            ldsm4(bl, bAddr + (bL - bH));
            mma16816(acc[np * 2],     ah, bh);
            mma16816(acc[np * 2],     ah, bl);
            mma16816(acc[np * 2],     al, bh);
            mma16816(acc[np * 2 + 1], ah, bh + 2);
            mma16816(acc[np * 2 + 1], ah, bl + 2);
            mma16816(acc[np * 2 + 1], al, bh + 2);
        }
    }
}

// ---------------------------------------------------------------------------
// fused gather + operand prep. grid 5576:
//  [0,4096): per-batch gather -> g_sh/g_sl, l_p_in, zero l_z
//  [4096,4480): W0  [4480,4992): W1  [4992,5120): W2
//  [5120,5320): LS split x4   [5320,5576): quad split x4
// ---------------------------------------------------------------------------
__device__ __forceinline__ void wsplit(const float* W, __nv_bfloat16* th,
                                       __nv_bfloat16* tl, int K, int N, int o) {
    int n = o / K, k = o % K;
    float v = W[k * N + n];
    __nv_bfloat16 h = __float2bfloat16_rn(v);
    th[o] = h;
    tl[o] = __float2bfloat16_rn(v - __bfloat162float(h));
}

__device__ __forceinline__ void vsplit4(const float* __restrict__ src,
                                        __nv_bfloat16* __restrict__ th,
                                        __nv_bfloat16* __restrict__ tl, long o4) {
    float4 v = *reinterpret_cast<const float4*>(&src[o4 * 4]);
    uint32_t h0, l0, h1, l1;
    split2(v.x, v.y, h0, l0);
    split2(v.z, v.w, h1, l1);
    *reinterpret_cast<uint2*>(&th[o4 * 4]) = make_uint2(h0, h1);
    *reinterpret_cast<uint2*>(&tl[o4 * 4]) = make_uint2(l0, l1);
}

__global__ void prep_gather(const float* __restrict__ fv,
                            const int* __restrict__ idx,
                            const float* __restrict__ emb,
                            const float* __restrict__ theta,
                            const float* __restrict__ W0, const float* __restrict__ W1,
                            const float* __restrict__ W2, const float* __restrict__ LS,
                            const float* __restrict__ quad)
{
    const int blk = blockIdx.x;
    const int t = threadIdx.x;
    if (blk >= 4096) {
        const int b = blk - 4096;
        if (b < 384)       wsplit(W0, g_w0h, g_w0l, 192, 512, b * 256 + t);
        else if (b < 896)  wsplit(W1, g_w1h, g_w1l, 512, 256, (b - 384) * 256 + t);
        else if (b < 1024) wsplit(W2, g_w2h, g_w2l, 256, 128, (b - 896) * 256 + t);
        else if (b < 1224) vsplit4(LS,   g_lsh, g_lsl, (long)(b - 1024) * 256 + t);
        else               vsplit4(quad, g_qh,  g_ql,  (long)(b - 1224) * 256 + t);
        return;
    }

    const int b = blk;
    __shared__ float feats[50 * 65];
    __shared__ float sq[50];
    __shared__ int   sidx[50];
    __shared__ float sfv[50];

    if (t < 50) { sidx[t] = idx[b * 50 + t]; sfv[t] = fv[b * 50 + t]; }
    __syncthreads();
    for (int j = t; j < 800; j += 256) {          // float4-vectorized gather
        int n = j >> 4, m4 = (j & 15) * 4;
        float4 e = *reinterpret_cast<const float4*>(&emb[(long)sidx[n] * 64 + m4]);
        float s = sfv[n];
        feats[n * 65 + m4]     = e.x * s;
        feats[n * 65 + m4 + 1] = e.y * s;
        feats[n * 65 + m4 + 2] = e.z * s;
        feats[n * 65 + m4 + 3] = e.w * s;
    }
    __syncthreads();
    if (t < 64) {   // s + exact bf16 split
        float acc = 0.f;
        #pragma unroll
        for (int n = 0; n < 50; n++) acc += feats[n * 65 + t];
        __nv_bfloat16 h = __float2bfloat16_rn(acc);
        g_sh[b * 64 + t] = h;
        g_sl[b * 64 + t] = __float2bfloat16_rn(acc - __bfloat162float(h));
        g_x[b * 192 + t] = 0.f;   // zero l_z accumulation slot
    }
    if (t >= 64 && t < 114) {
        int n = t - 64;
        float acc = 0.f;
        #pragma unroll
        for (int m = 0; m < 64; m++) { float v = feats[n * 65 + m]; acc += v * v; }
        sq[n] = acc;
    }
    __syncthreads();
    if (t < 64) {   // l_p_in
        float acc = 0.f;
        #pragma unroll
        for (int n = 0; n < 50; n++) { float th = theta[t * 50 + n]; acc += th * th * sq[n]; }
        g_x[b * 192 + 64 + t] = acc;
    }
}

// ============ lz / opnn tile layout =========================================
#define T_AL  18432          // A-lo offset (A tile 128 rows x 144B)
#define T_BH  36864          // B-hi offset
#define T_BL64 46080         // B-lo offset for 64-row B
#define BUF64 55296          // A(hi,lo) + 64-row B(hi,lo)

// ---------------------------------------------------------------------------
// l_z: C[b,d] += sum_n fv[b,n] * (emb[idx[b,n]] . LS[d,n,:]).
// A staged straight from fp32 emb with inline split (overlapped by double
// buffering; 2 blocks/SM). grid (32 row-tiles, 8 k-splits).
// ---------------------------------------------------------------------------
__global__ void __launch_bounds__(256) lz_mma(const float* __restrict__ fv,
                                              const int* __restrict__ idx,
                                              const float* __restrict__ emb)
{
    extern __shared__ char sm[];
    const int tid = threadIdx.x, wid = tid >> 5, lane = tid & 31;
    const uint32_t sb = smem_u32(sm);
    const int rowBase = blockIdx.x * 128;
    const int y = blockIdx.y;
    const int start = y * 6 + min(y, 2);
    const int count = (y < 2) ? 7 : 6;
    const int wrow = wid * 16;

    float acc[8][4];
    #pragma unroll
    for (int i = 0; i < 8; i++)
        #pragma unroll
        for (int j = 0; j < 4; j++) acc[i][j] = 0.f;

    auto stage = [&](int buf, int ci) {
        char* base = sm + buf * BUF64;
        const int n = start + ci;
        #pragma unroll
        for (int p = 0; p < 4; p++) {            // A hi/lo: gather fp32 emb + split
            int j = tid + p * 256;
            int r = j >> 3, q = j & 7;
            long eo = (long)idx[(rowBase + r) * 50 + n] * 64 + q * 8;
            float4 v0 = *reinterpret_cast<const float4*>(&emb[eo]);
            float4 v1 = *reinterpret_cast<const float4*>(&emb[eo + 4]);
            uint32_t h0, l0, h1, l1, h2, l2, h3, l3;
            split2(v0.x, v0.y, h0, l0);
            split2(v0.z, v0.w, h1, l1);
            split2(v1.x, v1.y, h2, l2);
            split2(v1.z, v1.w, h3, l3);
            *reinterpret_cast<uint4*>(base + r * PITCH + q * 16) =
                make_uint4(h0, h1, h2, h3);
            *reinterpret_cast<uint4*>(base + T_AL + r * PITCH + q * 16) =
                make_uint4(l0, l1, l2, l3);
        }
        #pragma unroll
        for (int p = 0; p < 2; p++) {            // B hi/lo: LS copy
            int j = tid + p * 256;
            int d = j >> 3, q = j & 7;
            long off = (long)d * 3200 + n * 64 + q * 8;
            *reinterpret_cast<uint4*>(base + T_BH + d * PITCH + q * 16) =
                *reinterpret_cast<const uint4*>(&g_lsh[off]);
            *reinterpret_cast<uint4*>(base + T_BL64 + d * PITCH + q * 16) =
                *reinterpret_cast<const uint4*>(&g_lsl[off]);
        }
    };

    const int lr = wrow + (lane >> 2);           // local row of acc[..][0,1]
    stage(0, 0);
    __syncthreads();
    for (int ci = 0; ci < count; ci++) {
        if (ci + 1 < count) stage((ci + 1) & 1, ci + 1);
        uint32_t cb = sb + (ci & 1) * BUF64;
        float cs[8][4];
        #pragma unroll
        for (int i = 0; i < 8; i++)
            #pragma unroll
            for (int j = 0; j < 4; j++) cs[i][j] = 0.f;
        warp_compute<8>(cb, cb + T_AL, cb + T_BH, cb + T_BL64, lane, wrow, cs);
        const int n = start + ci;
        const float fa = fv[(rowBase + lr) * 50 + n];
        const float fb = fv[(rowBase + lr + 8) * 50 + n];
        #pragma unroll
        for (int nt = 0; nt < 8; nt++) {
            acc[nt][0] += fa * cs[nt][0];
            acc[nt][1] += fa * cs[nt][1];
            acc[nt][2] += fb * cs[nt][2];
            acc[nt][3] += fb * cs[nt][3];
        }
        __syncthreads();
    }

    const int row0 = rowBase + lr;
    #pragma unroll
    for (int nt = 0; nt < 8; nt++) {
        const int col = nt * 8 + (lane & 3) * 2;
        atomicAdd(&g_x[row0 * 192 + col],           acc[nt][0]);
        atomicAdd(&g_x[row0 * 192 + col + 1],       acc[nt][1]);
        atomicAdd(&g_x[(row0 + 8) * 192 + col],     acc[nt][2]);
        atomicAdd(&g_x[(row0 + 8) * 192 + col + 1], acc[nt][3]);
    }
}

// ---------------------------------------------------------------------------
// l_p_out via T-GEMM: T[b, d*64+m] = sum_n s[b,n]*quad[d,m,n] (quad flat
// [4096,64] IS the K-major B), epilogue contracts sum_m s[b,m]*T.
// ONE K-stage, pure copies, no atomics. grid (32, 32). 73728 B smem.
// ---------------------------------------------------------------------------
__global__ void __launch_bounds__(256) opnn_mma()
{
    extern __shared__ char sm[];
    const int tid = threadIdx.x, wid = tid >> 5, lane = tid & 31;
    const uint32_t sb = smem_u32(sm);
    const int rowBase = blockIdx.x * 128;
    const int colBase = blockIdx.y * 128;
    const int wrow = wid * 16;

    #pragma unroll
    for (int p = 0; p < 4; p++) {                // A hi/lo from s split
        int j = tid + p * 256;
        int r = j >> 3, q = j & 7;
        long off = (long)(rowBase + r) * 64 + q * 8;
        *reinterpret_cast<uint4*>(sm + r * PITCH + q * 16) =
            *reinterpret_cast<const uint4*>(&g_sh[off]);
        *reinterpret_cast<uint4*>(sm + T_AL + r * PITCH + q * 16) =
            *reinterpret_cast<const uint4*>(&g_sl[off]);
    }
    #pragma unroll
    for (int p = 0; p < 4; p++) {                // B hi/lo from quad split
        int j = tid + p * 256;
        int d = j >> 3, q = j & 7;
        long off = (long)(colBase + d) * 64 + q * 8;
        *reinterpret_cast<uint4*>(sm + T_BH + d * PITCH + q * 16) =
            *reinterpret_cast<const uint4*>(&g_qh[off]);
        *reinterpret_cast<uint4*>(sm + 55296 + d * PITCH + q * 16) =
            *reinterpret_cast<const uint4*>(&g_ql[off]);
    }
    __syncthreads();

    float acc[16][4];
    #pragma unroll
    for (int i = 0; i < 16; i++)
        #pragma unroll
        for (int j = 0; j < 4; j++) acc[i][j] = 0.f;

    warp_compute<16>(sb, sb + T_AL, sb + T_BH, sb + 55296, lane, wrow, acc);

    const int lr0 = wrow + (lane >> 2);
    float part[4] = {0.f, 0.f, 0.f, 0.f};
    #pragma unroll
    for (int h = 0; h < 2; h++) {
        #pragma unroll
        for (int nt = 0; nt < 8; nt++) {
            const int a = h * 8 + nt;
            const int m = nt * 8 + (lane & 3) * 2;
            __nv_bfloat162 h0 = *reinterpret_cast<__nv_bfloat162*>(sm + lr0 * PITCH + m * 2);
            __nv_bfloat162 l0 = *reinterpret_cast<__nv_bfloat162*>(sm + T_AL + lr0 * PITCH + m * 2);
            __nv_bfloat162 h1 = *reinterpret_cast<__nv_bfloat162*>(sm + (lr0 + 8) * PITCH + m * 2);
            __nv_bfloat162 l1 = *reinterpret_cast<__nv_bfloat162*>(sm + T_AL + (lr0 + 8) * PITCH + m * 2);
            part[h * 2]     += acc[a][0] * (__bfloat162float(h0.x) + __bfloat162float(l0.x))
                             + acc[a][1] * (__bfloat162float(h0.y) + __bfloat162float(l0.y));
            part[h * 2 + 1] += acc[a][2] * (__bfloat162float(h1.x) + __bfloat162float(l1.x))
                             + acc[a][3] * (__bfloat162float(h1.y) + __bfloat162float(l1.y));
        }
    }
    #pragma unroll
    for (int i = 0; i < 4; i++) {
        part[i] += __shfl_xor_sync(0xffffffffu, part[i], 1);
        part[i] += __shfl_xor_sync(0xffffffffu, part[i], 2);
    }
    if ((lane & 3) == 0) {
        const int d0 = colBase >> 6;
        g_x[(rowBase + lr0) * 192 + 128 + d0]         = part[0];
        g_x[(rowBase + lr0) * 192 + 128 + d0 + 1]     = part[2];
        g_x[(rowBase + lr0 + 8) * 192 + 128 + d0]     = part[1];
        g_x[(rowBase + lr0 + 8) * 192 + 128 + d0 + 1] = part[3];
    }
}

// ---------------------------------------------------------------------------
// MLP layer: C = A @ W^T + BN + ReLU.  BM=64, 128 threads (4 warps x 16 rows)
// -> 2-4 blocks/SM, grid (N/(NT*8), 64) = 256 blocks. AF32=1 stages A from
// fp32 with inline split.
// ---------------------------------------------------------------------------
template<int NT, int OUT_SPLIT, int AF32>
__global__ void __launch_bounds__(128) mlp_mma(
    const float* __restrict__ af,
    const __nv_bfloat16* __restrict__ ah, const __nv_bfloat16* __restrict__ al,
    const __nv_bfloat16* __restrict__ wh, const __nv_bfloat16* __restrict__ wl,
    __nv_bfloat16* __restrict__ oh, __nv_bfloat16* __restrict__ ol,
    float* __restrict__ of, int K, int N,
    const float* __restrict__ bias, const float* __restrict__ gam,
    const float* __restrict__ bet, const float* __restrict__ mu,
    const float* __restrict__ var)
{
    constexpr int BROWS = NT * 8;
    constexpr int BB    = BROWS * PITCH;
    constexpr int AB    = 64 * PITCH;          // 9216 per A buffer
    constexpr int OAL   = AB;                  // A-lo
    constexpr int OBH   = 2 * AB;              // 18432
    constexpr int OBL   = 2 * AB + BB;
    constexpr int BUFSZ = 2 * AB + 2 * BB;

    extern __shared__ char sm[];
    const int tid = threadIdx.x, wid = tid >> 5, lane = tid & 31;
    const uint32_t sb = smem_u32(sm);
    float* sscale = reinterpret_cast<float*>(sm + 2 * BUFSZ);
    float* sshift = sscale + BROWS;
    const int rowBase = blockIdx.y * 64;
    const int colBase = blockIdx.x * BROWS;
    const int wrow = wid * 16;

    if (tid < BROWS) {
        int c = colBase + tid;
        float sc = gam[c] * rsqrtf(var[c] + 1e-3f);
        sscale[tid] = sc;
        sshift[tid] = (bias[c] - mu[c]) * sc + bet[c];
    }

    float acc[NT][4];
    #pragma unroll
    for (int i = 0; i < NT; i++)
        #pragma unroll
        for (int j = 0; j < 4; j++) acc[i][j] = 0.f;

    const int nch = K >> 6;
    auto stage = [&](int buf, int ch) {
        char* base = sm + buf * BUFSZ;
        const int k0 = ch * 64;
        #pragma unroll
        for (int p = 0; p < 4; p++) {            // A: 64 rows x 8 q / 128 thr
            int j = tid + p * 128;
            int r = j >> 3, q = j & 7;
            long off = (long)(rowBase + r) * K + k0 + q * 8;
            if (AF32) {
                float4 v0 = *reinterpret_cast<const float4*>(&af[off]);
                float4 v1 = *reinterpret_cast<const float4*>(&af[off + 4]);
                uint32_t h0, l0, h1, l1, h2, l2, h3, l3;
                split2(v0.x, v0.y, h0, l0);
                split2(v0.z, v0.w, h1, l1);
                split2(v1.x, v1.y, h2, l2);
                split2(v1.z, v1.w, h3, l3);
                *reinterpret_cast<uint4*>(base + r * PITCH + q * 16) =
                    make_uint4(h0, h1, h2, h3);
                *reinterpret_cast<uint4*>(base + OAL + r * PITCH + q * 16) =
                    make_uint4(l0, l1, l2, l3);
            } else {
                *reinterpret_cast<uint4*>(base + r * PITCH + q * 16) =
                    *reinterpret_cast<const uint4*>(&ah[off]);
                *reinterpret_cast<uint4*>(base + OAL + r * PITCH + q * 16) =
                    *reinterpret_cast<const uint4*>(&al[off]);
            }
        }
        #pragma unroll
        for (int p = 0; p < NT / 2; p++) {       // B: BROWS x 8 q / 128 thr
            int j = tid + p * 128;
            int d = j >> 3, q = j & 7;
            long off = (long)(colBase + d) * K + k0 + q * 8;
            *reinterpret_cast<uint4*>(base + OBH + d * PITCH + q * 16) =
                *reinterpret_cast<const uint4*>(&wh[off]);
            *reinterpret_cast<uint4*>(base + OBL + d * PITCH + q * 16) =
                *reinterpret_cast<const uint4*>(&wl[off]);
        }
    };

    stage(0, 0);
    __syncthreads();
    for (int ch = 0; ch < nch; ch++) {
        if (ch + 1 < nch) stage((ch + 1) & 1, ch + 1);
        uint32_t cb = sb + (ch & 1) * BUFSZ;
        warp_compute<NT>(cb, cb + OAL, cb + OBH, cb + OBL, lane, wrow, acc);
        __syncthreads();
    }

    const int row0 = rowBase + wrow + (lane >> 2);
    #pragma unroll
    for (int nt = 0; nt < NT; nt++) {
        const int cl = nt * 8 + (lane & 3) * 2;
        const float s0 = sscale[cl], s1 = sscale[cl + 1];
        const float t0 = sshift[cl], t1 = sshift[cl + 1];
        float v0 = fmaxf(acc[nt][0] * s0 + t0, 0.f);
        float v1 = fmaxf(acc[nt][1] * s1 + t1, 0.f);
        float v2 = fmaxf(acc[nt][2] * s0 + t0, 0.f);
        float v3 = fmaxf(acc[nt][3] * s1 + t1, 0.f);
        if (OUT_SPLIT) {
            uint32_t h, l;
            split2(v0, v1, h, l);
            *reinterpret_cast<uint32_t*>(&oh[(long)row0 * N + colBase + cl]) = h;
            *reinterpret_cast<uint32_t*>(&ol[(long)row0 * N + colBase + cl]) = l;
            split2(v2, v3, h, l);
            *reinterpret_cast<uint32_t*>(&oh[(long)(row0 + 8) * N + colBase + cl]) = h;
            *reinterpret_cast<uint32_t*>(&ol[(long)(row0 + 8) * N + colBase + cl]) = l;
        } else {
            *reinterpret_cast<float2*>(&of[(long)row0 * N + colBase + cl]) = make_float2(v0, v1);
            *reinterpret_cast<float2*>(&of[(long)(row0 + 8) * N + colBase + cl]) = make_float2(v2, v3);
        }
    }
}

// ---------------------------------------------------------------------------
// final dense [4096,128]@[128,1] + sigmoid
// ---------------------------------------------------------------------------
__global__ void final_kernel(const float* __restrict__ Wout,
                             const float* __restrict__ bout,
                             float* __restrict__ out)
{
    const int warp = (blockIdx.x * blockDim.x + threadIdx.x) >> 5;
    const int lane = threadIdx.x & 31;
    if (warp >= BATCH) return;
    const float* h = &g_h2[warp * 128];
    float acc = h[lane]      * Wout[lane]
              + h[lane + 32] * Wout[lane + 32]
              + h[lane + 64] * Wout[lane + 64]
              + h[lane + 96] * Wout[lane + 96];
    #pragma unroll
    for (int off = 16; off > 0; off >>= 1)
        acc += __shfl_down_sync(0xffffffffu, acc, off);
    if (lane == 0) {
        float z = acc + bout[0];
        out[warp] = 1.f / (1.f + expf(-z));
    }
}

// ---------------------------------------------------------------------------
extern "C" void kernel_launch(void* const* d_in, const int* in_sizes, int n_in,
                              void* d_out, int out_size)
{
    const float* fv    = (const float*)d_in[0];
    const int*   idx   = (const int*)  d_in[1];
    const float* emb   = (const float*)d_in[2];
    const float* LS    = (const float*)d_in[3];
    const float* theta = (const float*)d_in[4];
    const float* quad  = (const float*)d_in[5];
    const float* W0  = (const float*)d_in[6];
    const float* b0  = (const float*)d_in[7];
    const float* gm0 = (const float*)d_in[8];
    const float* be0 = (const float*)d_in[9];
    const float* m0  = (const float*)d_in[10];
    const float* v0  = (const float*)d_in[11];
    const float* W1  = (const float*)d_in[12];
    const float* b1  = (const float*)d_in[13];
    const float* gm1 = (const float*)d_in[14];
    const float* be1 = (const float*)d_in[15];
    const float* m1  = (const float*)d_in[16];
    const float* v1  = (const float*)d_in[17];
    const float* W2  = (const float*)d_in[18];
    const float* b2  = (const float*)d_in[19];
    const float* gm2 = (const float*)d_in[20];
    const float* be2 = (const float*)d_in[21];
    const float* m2  = (const float*)d_in[22];
    const float* v2  = (const float*)d_in[23];
    const float* Wout = (const float*)d_in[24];
    const float* bout = (const float*)d_in[25];
    float* out = (float*)d_out;

    float *p_x, *p_h2;
    __nv_bfloat16 *p_h0h, *p_h0l, *p_h1h, *p_h1l;
    __nv_bfloat16 *p_w0h, *p_w0l, *p_w1h, *p_w1l, *p_w2h, *p_w2l;
    cudaGetSymbolAddress((void**)&p_x,   g_x);
    cudaGetSymbolAddress((void**)&p_h0h, g_h0h);
    cudaGetSymbolAddress((void**)&p_h0l, g_h0l);
    cudaGetSymbolAddress((void**)&p_h1h, g_h1h);
    cudaGetSymbolAddress((void**)&p_h1l, g_h1l);
    cudaGetSymbolAddress((void**)&p_h2,  g_h2);
    cudaGetSymbolAddress((void**)&p_w0h, g_w0h);
    cudaGetSymbolAddress((void**)&p_w0l, g_w0l);
    cudaGetSymbolAddress((void**)&p_w1h, g_w1h);
    cudaGetSymbolAddress((void**)&p_w1l, g_w1l);
    cudaGetSymbolAddress((void**)&p_w2h, g_w2h);
    cudaGetSymbolAddress((void**)&p_w2l, g_w2l);

    const int SMEM_LZ    = 2 * BUF64;                          // 110592 -> 2/SM
    const int SMEM_OP    = 73728;                              // 3/SM
    const int SMEM_MLP16 = 2 * (18432 + 2 * 128 * PITCH) + 1024;   // 111616 -> 2/SM
    const int SMEM_MLP8  = 2 * (18432 + 2 * 64 * PITCH) + 1024;    //  74752 -> 3/SM
    const int SMEM_MLP4  = 2 * (18432 + 2 * 32 * PITCH) + 1024;    //  56320 -> 4/SM
    cudaFuncSetAttribute(lz_mma,          cudaFuncAttributeMaxDynamicSharedMemorySize, SMEM_LZ);
    cudaFuncSetAttribute(opnn_mma,        cudaFuncAttributeMaxDynamicSharedMemorySize, SMEM_OP);
    cudaFuncSetAttribute(mlp_mma<16,1,1>, cudaFuncAttributeMaxDynamicSharedMemorySize, SMEM_MLP16);
    cudaFuncSetAttribute(mlp_mma<8,1,0>,  cudaFuncAttributeMaxDynamicSharedMemorySize, SMEM_MLP8);
    cudaFuncSetAttribute(mlp_mma<4,0,0>,  cudaFuncAttributeMaxDynamicSharedMemorySize, SMEM_MLP4);

    // 1) fused gather + operand prep (no emb split any more)
    prep_gather<<<5576, 256>>>(fv, idx, emb, theta, W0, W1, W2, LS, quad);
    // 2) l_z (fp32 emb gather + inline split, 2 blocks/SM)
    lz_mma<<<dim3(32, 8), 256, SMEM_LZ>>>(fv, idx, emb);
    // 3) l_p_out (single-K-stage T-GEMM + in-register contraction)
    opnn_mma<<<dim3(32, 32), 256, SMEM_OP>>>();
    // 4) MLP (BM=64, 128 threads, 256 blocks per layer)
    mlp_mma<16,1,1><<<dim3(4, 64), 128, SMEM_MLP16>>>(p_x, nullptr, nullptr,
        p_w0h, p_w0l, p_h0h, p_h0l, nullptr, 192, 512, b0, gm0, be0, m0, v0);
    mlp_mma<8,1,0><<<dim3(4, 64), 128, SMEM_MLP8>>>(nullptr, p_h0h, p_h0l,
        p_w1h, p_w1l, p_h1h, p_h1l, nullptr, 512, 256, b1, gm1, be1, m1, v1);
    mlp_mma<4,0,0><<<dim3(4, 64), 128, SMEM_MLP4>>>(nullptr, p_h1h, p_h1l,
        p_w2h, p_w2l, nullptr, nullptr, p_h2, 256, 128, b2, gm2, be2, m2, v2);
    // 5) output + sigmoid
    final_kernel<<<BATCH * 32 / 256, 256>>>(Wout, bout, out);
}

// round 17
// speedup vs baseline: 1.0536x; 1.0181x over previous
#include <cuda_runtime.h>
#include <cuda_bf16.h>
#include <cstdint>
#include <math.h>

#define BATCH 4096
#define PITCH 144            // bf16 tile row pitch (9 x 16B, ldsm conflict-free)

// ---------------- device scratch ------------------------------------------
__device__ __align__(16) float g_x[4096 * 192];
__device__ __align__(16) __nv_bfloat16 g_sh[4096 * 64],  g_sl[4096 * 64];
__device__ __align__(16) __nv_bfloat16 g_h0h[4096 * 512], g_h0l[4096 * 512];
__device__ __align__(16) __nv_bfloat16 g_h1h[4096 * 256], g_h1l[4096 * 256];
__device__ float g_h2[4096 * 128];
__device__ __align__(16) __nv_bfloat16 g_w0h[512 * 192], g_w0l[512 * 192];
__device__ __align__(16) __nv_bfloat16 g_w1h[256 * 512], g_w1l[256 * 512];
__device__ __align__(16) __nv_bfloat16 g_w2h[128 * 256], g_w2l[128 * 256];
__device__ __align__(16) __nv_bfloat16 g_lsh[64 * 3200], g_lsl[64 * 3200];
__device__ __align__(16) __nv_bfloat16 g_qh[4096 * 64],  g_ql[4096 * 64];

// ---------------- helpers --------------------------------------------------
__device__ __forceinline__ uint32_t smem_u32(const void* p) {
    uint32_t a;
    asm("{ .reg .u64 t; cvta.to.shared.u64 t, %1; cvt.u32.u64 %0, t; }" : "=r"(a) : "l"(p));
    return a;
}

__device__ __forceinline__ void split2(float a, float b, uint32_t& h, uint32_t& l) {
    __nv_bfloat162 hh = __floats2bfloat162_rn(a, b);
    float ra = a - __bfloat162float(hh.x);
    float rb = b - __bfloat162float(hh.y);
    __nv_bfloat162 ll = __floats2bfloat162_rn(ra, rb);
    h = *reinterpret_cast<uint32_t*>(&hh);
    l = *reinterpret_cast<uint32_t*>(&ll);
}

__device__ __forceinline__ void ldsm4(uint32_t* r, uint32_t addr) {
    asm volatile("ldmatrix.sync.aligned.m8n8.x4.shared.b16 {%0,%1,%2,%3}, [%4];"
                 : "=r"(r[0]), "=r"(r[1]), "=r"(r[2]), "=r"(r[3]) : "r"(addr));
}

__device__ __forceinline__ void mma16816(float* c, const uint32_t* a, const uint32_t* b) {
    asm volatile(
        "mma.sync.aligned.m16n8k16.row.col.f32.bf16.bf16.f32 "
        "{%0,%1,%2,%3}, {%4,%5,%6,%7}, {%8,%9}, {%0,%1,%2,%3};"
        : "+f"(c[0]), "+f"(c[1]), "+f"(c[2]), "+f"(c[3])
        : "r"(a[0]), "r"(a[1]), "r"(a[2]), "r"(a[3]), "r"(b[0]), "r"(b[1]));
}

// warp computes its 16 x (NT*8) C tile for one K=64 stage (3-product split)
template<int NT>
__device__ __forceinline__ void warp_compute(uint32_t aH, uint32_t aL,
                                             uint32_t bH, uint32_t bL,
                                             int lane, int wrow, float (*acc)[4]) {
    #pragma unroll
    for (int ks = 0; ks < 4; ks++) {
        const int k0 = ks * 16;
        uint32_t aAddr = aH + (wrow + (lane & 15)) * PITCH + (k0 + ((lane >> 4) & 1) * 8) * 2;
        uint32_t ah[4], al[4];
        ldsm4(ah, aAddr);
        ldsm4(al, aAddr + (aL - aH));
        #pragma unroll
        for (int np = 0; np < NT / 2; np++) {
            uint32_t bAddr = bH + (np * 16 + ((lane >> 4) & 1) * 8 + (lane & 7)) * PITCH
                           + (k0 + ((lane >> 3) & 1) * 8) * 2;
            uint32_t bh[4], bl[4];
            ldsm4(bh, bAddr);
            ldsm4(bl, bAddr + (bL - bH));
            mma16816(acc[np * 2],     ah, bh);
            mma16816(acc[np * 2],     ah, bl);
            mma16816(acc[np * 2],     al, bh);
            mma16816(acc[np * 2 + 1], ah, bh + 2);
            mma16816(acc[np * 2 + 1], ah, bl + 2);
            mma16816(acc[np * 2 + 1], al, bh + 2);
        }
    }
}

// ---------------------------------------------------------------------------
// fused gather + operand prep. grid 5576:
//  [0,4096): per-batch gather -> g_sh/g_sl, l_p_in, zero l_z
//  [4096,4480): W0  [4480,4992): W1  [4992,5120): W2
//  [5120,5320): LS split x4   [5320,5576): quad split x4
// ---------------------------------------------------------------------------
__device__ __forceinline__ void wsplit(const float* W, __nv_bfloat16* th,
                                       __nv_bfloat16* tl, int K, int N, int o) {
    int n = o / K, k = o % K;
    float v = W[k * N + n];
    __nv_bfloat16 h = __float2bfloat16_rn(v);
    th[o] = h;
    tl[o] = __float2bfloat16_rn(v - __bfloat162float(h));
}

__device__ __forceinline__ void vsplit4(const float* __restrict__ src,
                                        __nv_bfloat16* __restrict__ th,
                                        __nv_bfloat16* __restrict__ tl, long o4) {
    float4 v = *reinterpret_cast<const float4*>(&src[o4 * 4]);
    uint32_t h0, l0, h1, l1;
    split2(v.x, v.y, h0, l0);
    split2(v.z, v.w, h1, l1);
    *reinterpret_cast<uint2*>(&th[o4 * 4]) = make_uint2(h0, h1);
    *reinterpret_cast<uint2*>(&tl[o4 * 4]) = make_uint2(l0, l1);
}

__global__ void prep_gather(const float* __restrict__ fv,
                            const int* __restrict__ idx,
                            const float* __restrict__ emb,
                            const float* __restrict__ theta,
                            const float* __restrict__ W0, const float* __restrict__ W1,
                            const float* __restrict__ W2, const float* __restrict__ LS,
                            const float* __restrict__ quad)
{
    const int blk = blockIdx.x;
    const int t = threadIdx.x;
    if (blk >= 4096) {
        const int b = blk - 4096;
        if (b < 384)       wsplit(W0, g_w0h, g_w0l, 192, 512, b * 256 + t);
        else if (b < 896)  wsplit(W1, g_w1h, g_w1l, 512, 256, (b - 384) * 256 + t);
        else if (b < 1024) wsplit(W2, g_w2h, g_w2l, 256, 128, (b - 896) * 256 + t);
        else if (b < 1224) vsplit4(LS,   g_lsh, g_lsl, (long)(b - 1024) * 256 + t);
        else               vsplit4(quad, g_qh,  g_ql,  (long)(b - 1224) * 256 + t);
        return;
    }

    const int b = blk;
    __shared__ float feats[50 * 65];
    __shared__ float sq[50];
    __shared__ int   sidx[50];
    __shared__ float sfv[50];

    if (t < 50) { sidx[t] = idx[b * 50 + t]; sfv[t] = fv[b * 50 + t]; }
    __syncthreads();
    for (int j = t; j < 800; j += 256) {          // float4-vectorized gather
        int n = j >> 4, m4 = (j & 15) * 4;
        float4 e = *reinterpret_cast<const float4*>(&emb[(long)sidx[n] * 64 + m4]);
        float s = sfv[n];
        feats[n * 65 + m4]     = e.x * s;
        feats[n * 65 + m4 + 1] = e.y * s;
        feats[n * 65 + m4 + 2] = e.z * s;
        feats[n * 65 + m4 + 3] = e.w * s;
    }
    __syncthreads();
    if (t < 64) {   // s + exact bf16 split
        float acc = 0.f;
        #pragma unroll
        for (int n = 0; n < 50; n++) acc += feats[n * 65 + t];
        __nv_bfloat16 h = __float2bfloat16_rn(acc);
        g_sh[b * 64 + t] = h;
        g_sl[b * 64 + t] = __float2bfloat16_rn(acc - __bfloat162float(h));
        g_x[b * 192 + t] = 0.f;   // zero l_z accumulation slot
    }
    if (t >= 64 && t < 114) {
        int n = t - 64;
        float acc = 0.f;
        #pragma unroll
        for (int m = 0; m < 64; m++) { float v = feats[n * 65 + m]; acc += v * v; }
        sq[n] = acc;
    }
    __syncthreads();
    if (t < 64) {   // l_p_in
        float acc = 0.f;
        #pragma unroll
        for (int n = 0; n < 50; n++) { float th = theta[t * 50 + n]; acc += th * th * sq[n]; }
        g_x[b * 192 + 64 + t] = acc;
    }
}

// ============ lz / opnn tile layout =========================================
#define T_AL  18432          // A-lo offset (A tile 128 rows x 144B)
#define T_BH  36864          // B-hi offset
#define T_BL64 46080         // B-lo offset for 64-row B
#define BUF64 55296          // A(hi,lo) + 64-row B(hi,lo)

// ---------------------------------------------------------------------------
// merged lz + opnn kernel. grid 1280:
//  blocks [0,256):  lz   (rowTile = bx & 31, ksplit y = bx >> 5)
//  blocks [256,1280): opnn (o = bx-256; rowTile = o & 31, colTile = o >> 5)
// Both write disjoint column ranges of g_x; both depend only on prep.
// smem request: 110592 (lz needs 2*BUF64; opnn uses first 73728 bytes).
// ---------------------------------------------------------------------------
__global__ void __launch_bounds__(256) lzop_mma(const float* __restrict__ fv,
                                                const int* __restrict__ idx,
                                                const float* __restrict__ emb)
{
    extern __shared__ char sm[];
    const int tid = threadIdx.x, wid = tid >> 5, lane = tid & 31;
    const uint32_t sb = smem_u32(sm);
    const int wrow = wid * 16;

    if (blockIdx.x < 256) {
        // ------------------------- lz role --------------------------------
        const int rowBase = (blockIdx.x & 31) * 128;
        const int y = blockIdx.x >> 5;
        const int start = y * 6 + min(y, 2);
        const int count = (y < 2) ? 7 : 6;

        float acc[8][4];
        #pragma unroll
        for (int i = 0; i < 8; i++)
            #pragma unroll
            for (int j = 0; j < 4; j++) acc[i][j] = 0.f;

        auto stage = [&](int buf, int ci) {
            char* base = sm + buf * BUF64;
            const int n = start + ci;
            #pragma unroll
            for (int p = 0; p < 4; p++) {        // A hi/lo: fp32 emb gather + split
                int j = tid + p * 256;
                int r = j >> 3, q = j & 7;
                long eo = (long)idx[(rowBase + r) * 50 + n] * 64 + q * 8;
                float4 v0 = *reinterpret_cast<const float4*>(&emb[eo]);
                float4 v1 = *reinterpret_cast<const float4*>(&emb[eo + 4]);
                uint32_t h0, l0, h1, l1, h2, l2, h3, l3;
                split2(v0.x, v0.y, h0, l0);
                split2(v0.z, v0.w, h1, l1);
                split2(v1.x, v1.y, h2, l2);
                split2(v1.z, v1.w, h3, l3);
                *reinterpret_cast<uint4*>(base + r * PITCH + q * 16) =
                    make_uint4(h0, h1, h2, h3);
                *reinterpret_cast<uint4*>(base + T_AL + r * PITCH + q * 16) =
                    make_uint4(l0, l1, l2, l3);
            }
            #pragma unroll
            for (int p = 0; p < 2; p++) {        // B hi/lo: LS copy
                int j = tid + p * 256;
                int d = j >> 3, q = j & 7;
                long off = (long)d * 3200 + n * 64 + q * 8;
                *reinterpret_cast<uint4*>(base + T_BH + d * PITCH + q * 16) =
                    *reinterpret_cast<const uint4*>(&g_lsh[off]);
                *reinterpret_cast<uint4*>(base + T_BL64 + d * PITCH + q * 16) =
                    *reinterpret_cast<const uint4*>(&g_lsl[off]);
            }
        };

        const int lr = wrow + (lane >> 2);
        stage(0, 0);
        __syncthreads();
        for (int ci = 0; ci < count; ci++) {
            if (ci + 1 < count) stage((ci + 1) & 1, ci + 1);
            uint32_t cb = sb + (ci & 1) * BUF64;
            float cs[8][4];
            #pragma unroll
            for (int i = 0; i < 8; i++)
                #pragma unroll
                for (int j = 0; j < 4; j++) cs[i][j] = 0.f;
            warp_compute<8>(cb, cb + T_AL, cb + T_BH, cb + T_BL64, lane, wrow, cs);
            const int n = start + ci;
            const float fa = fv[(rowBase + lr) * 50 + n];
            const float fb = fv[(rowBase + lr + 8) * 50 + n];
            #pragma unroll
            for (int nt = 0; nt < 8; nt++) {
                acc[nt][0] += fa * cs[nt][0];
                acc[nt][1] += fa * cs[nt][1];
                acc[nt][2] += fb * cs[nt][2];
                acc[nt][3] += fb * cs[nt][3];
            }
            __syncthreads();
        }

        const int row0 = rowBase + lr;
        #pragma unroll
        for (int nt = 0; nt < 8; nt++) {
            const int col = nt * 8 + (lane & 3) * 2;
            atomicAdd(&g_x[row0 * 192 + col],           acc[nt][0]);
            atomicAdd(&g_x[row0 * 192 + col + 1],       acc[nt][1]);
            atomicAdd(&g_x[(row0 + 8) * 192 + col],     acc[nt][2]);
            atomicAdd(&g_x[(row0 + 8) * 192 + col + 1], acc[nt][3]);
        }
    } else {
        // ------------------------ opnn role -------------------------------
        const int o = blockIdx.x - 256;
        const int rowBase = (o & 31) * 128;
        const int colBase = (o >> 5) * 128;

        #pragma unroll
        for (int p = 0; p < 4; p++) {            // A hi/lo from s split
            int j = tid + p * 256;
            int r = j >> 3, q = j & 7;
            long off = (long)(rowBase + r) * 64 + q * 8;
            *reinterpret_cast<uint4*>(sm + r * PITCH + q * 16) =
                *reinterpret_cast<const uint4*>(&g_sh[off]);
            *reinterpret_cast<uint4*>(sm + T_AL + r * PITCH + q * 16) =
                *reinterpret_cast<const uint4*>(&g_sl[off]);
        }
        #pragma unroll
        for (int p = 0; p < 4; p++) {            // B hi/lo from quad split
            int j = tid + p * 256;
            int d = j >> 3, q = j & 7;
            long off = (long)(colBase + d) * 64 + q * 8;
            *reinterpret_cast<uint4*>(sm + T_BH + d * PITCH + q * 16) =
                *reinterpret_cast<const uint4*>(&g_qh[off]);
            *reinterpret_cast<uint4*>(sm + 55296 + d * PITCH + q * 16) =
                *reinterpret_cast<const uint4*>(&g_ql[off]);
        }
        __syncthreads();

        float acc[16][4];
        #pragma unroll
        for (int i = 0; i < 16; i++)
            #pragma unroll
            for (int j = 0; j < 4; j++) acc[i][j] = 0.f;

        warp_compute<16>(sb, sb + T_AL, sb + T_BH, sb + 55296, lane, wrow, acc);

        const int lr0 = wrow + (lane >> 2);
        float part[4] = {0.f, 0.f, 0.f, 0.f};
        #pragma unroll
        for (int h = 0; h < 2; h++) {
            #pragma unroll
            for (int nt = 0; nt < 8; nt++) {
                const int a = h * 8 + nt;
                const int m = nt * 8 + (lane & 3) * 2;
                __nv_bfloat162 h0 = *reinterpret_cast<__nv_bfloat162*>(sm + lr0 * PITCH + m * 2);
                __nv_bfloat162 l0 = *reinterpret_cast<__nv_bfloat162*>(sm + T_AL + lr0 * PITCH + m * 2);
                __nv_bfloat162 h1 = *reinterpret_cast<__nv_bfloat162*>(sm + (lr0 + 8) * PITCH + m * 2);
                __nv_bfloat162 l1 = *reinterpret_cast<__nv_bfloat162*>(sm + T_AL + (lr0 + 8) * PITCH + m * 2);
                part[h * 2]     += acc[a][0] * (__bfloat162float(h0.x) + __bfloat162float(l0.x))
                                 + acc[a][1] * (__bfloat162float(h0.y) + __bfloat162float(l0.y));
                part[h * 2 + 1] += acc[a][2] * (__bfloat162float(h1.x) + __bfloat162float(l1.x))
                                 + acc[a][3] * (__bfloat162float(h1.y) + __bfloat162float(l1.y));
            }
        }
        #pragma unroll
        for (int i = 0; i < 4; i++) {
            part[i] += __shfl_xor_sync(0xffffffffu, part[i], 1);
            part[i] += __shfl_xor_sync(0xffffffffu, part[i], 2);
        }
        if ((lane & 3) == 0) {
            const int d0 = colBase >> 6;
            g_x[(rowBase + lr0) * 192 + 128 + d0]         = part[0];
            g_x[(rowBase + lr0) * 192 + 128 + d0 + 1]     = part[2];
            g_x[(rowBase + lr0 + 8) * 192 + 128 + d0]     = part[1];
            g_x[(rowBase + lr0 + 8) * 192 + 128 + d0 + 1] = part[3];
        }
    }
}

// ---------------------------------------------------------------------------
// MLP layer: C = A @ W^T + BN + ReLU.  BM=64, 128 threads (4 warps x 16 rows).
// AF32=1 stages A from fp32 with inline split.
// ---------------------------------------------------------------------------
template<int NT, int OUT_SPLIT, int AF32>
__global__ void __launch_bounds__(128) mlp_mma(
    const float* __restrict__ af,
    const __nv_bfloat16* __restrict__ ah, const __nv_bfloat16* __restrict__ al,
    const __nv_bfloat16* __restrict__ wh, const __nv_bfloat16* __restrict__ wl,
    __nv_bfloat16* __restrict__ oh, __nv_bfloat16* __restrict__ ol,
    float* __restrict__ of, int K, int N,
    const float* __restrict__ bias, const float* __restrict__ gam,
    const float* __restrict__ bet, const float* __restrict__ mu,
    const float* __restrict__ var)
{
    constexpr int BROWS = NT * 8;
    constexpr int BB    = BROWS * PITCH;
    constexpr int AB    = 64 * PITCH;          // 9216 per A buffer
    constexpr int OAL   = AB;                  // A-lo
    constexpr int OBH   = 2 * AB;              // 18432
    constexpr int OBL   = 2 * AB + BB;
    constexpr int BUFSZ = 2 * AB + 2 * BB;

    extern __shared__ char sm[];
    const int tid = threadIdx.x, wid = tid >> 5, lane = tid & 31;
    const uint32_t sb = smem_u32(sm);
    float* sscale = reinterpret_cast<float*>(sm + 2 * BUFSZ);
    float* sshift = sscale + BROWS;
    const int rowBase = blockIdx.y * 64;
    const int colBase = blockIdx.x * BROWS;
    const int wrow = wid * 16;

    if (tid < BROWS) {
        int c = colBase + tid;
        float sc = gam[c] * rsqrtf(var[c] + 1e-3f);
        sscale[tid] = sc;
        sshift[tid] = (bias[c] - mu[c]) * sc + bet[c];
    }

    float acc[NT][4];
    #pragma unroll
    for (int i = 0; i < NT; i++)
        #pragma unroll
        for (int j = 0; j < 4; j++) acc[i][j] = 0.f;

    const int nch = K >> 6;
    auto stage = [&](int buf, int ch) {
        char* base = sm + buf * BUFSZ;
        const int k0 = ch * 64;
        #pragma unroll
        for (int p = 0; p < 4; p++) {            // A: 64 rows x 8 q / 128 thr
            int j = tid + p * 128;
            int r = j >> 3, q = j & 7;
            long off = (long)(rowBase + r) * K + k0 + q * 8;
            if (AF32) {
                float4 v0 = *reinterpret_cast<const float4*>(&af[off]);
                float4 v1 = *reinterpret_cast<const float4*>(&af[off + 4]);
                uint32_t h0, l0, h1, l1, h2, l2, h3, l3;
                split2(v0.x, v0.y, h0, l0);
                split2(v0.z, v0.w, h1, l1);
                split2(v1.x, v1.y, h2, l2);
                split2(v1.z, v1.w, h3, l3);
                *reinterpret_cast<uint4*>(base + r * PITCH + q * 16) =
                    make_uint4(h0, h1, h2, h3);
                *reinterpret_cast<uint4*>(base + OAL + r * PITCH + q * 16) =
                    make_uint4(l0, l1, l2, l3);
            } else {
                *reinterpret_cast<uint4*>(base + r * PITCH + q * 16) =
                    *reinterpret_cast<const uint4*>(&ah[off]);
                *reinterpret_cast<uint4*>(base + OAL + r * PITCH + q * 16) =
                    *reinterpret_cast<const uint4*>(&al[off]);
            }
        }
        #pragma unroll
        for (int p = 0; p < NT / 2; p++) {       // B: BROWS x 8 q / 128 thr
            int j = tid + p * 128;
            int d = j >> 3, q = j & 7;
            long off = (long)(colBase + d) * K + k0 + q * 8;
            *reinterpret_cast<uint4*>(base + OBH + d * PITCH + q * 16) =
                *reinterpret_cast<const uint4*>(&wh[off]);
            *reinterpret_cast<uint4*>(base + OBL + d * PITCH + q * 16) =
                *reinterpret_cast<const uint4*>(&wl[off]);
        }
    };

    stage(0, 0);
    __syncthreads();
    for (int ch = 0; ch < nch; ch++) {
        if (ch + 1 < nch) stage((ch + 1) & 1, ch + 1);
        uint32_t cb = sb + (ch & 1) * BUFSZ;
        warp_compute<NT>(cb, cb + OAL, cb + OBH, cb + OBL, lane, wrow, acc);
        __syncthreads();
    }

    const int row0 = rowBase + wrow + (lane >> 2);
    #pragma unroll
    for (int nt = 0; nt < NT; nt++) {
        const int cl = nt * 8 + (lane & 3) * 2;
        const float s0 = sscale[cl], s1 = sscale[cl + 1];
        const float t0 = sshift[cl], t1 = sshift[cl + 1];
        float v0 = fmaxf(acc[nt][0] * s0 + t0, 0.f);
        float v1 = fmaxf(acc[nt][1] * s1 + t1, 0.f);
        float v2 = fmaxf(acc[nt][2] * s0 + t0, 0.f);
        float v3 = fmaxf(acc[nt][3] * s1 + t1, 0.f);
        if (OUT_SPLIT) {
            uint32_t h, l;
            split2(v0, v1, h, l);
            *reinterpret_cast<uint32_t*>(&oh[(long)row0 * N + colBase + cl]) = h;
            *reinterpret_cast<uint32_t*>(&ol[(long)row0 * N + colBase + cl]) = l;
            split2(v2, v3, h, l);
            *reinterpret_cast<uint32_t*>(&oh[(long)(row0 + 8) * N + colBase + cl]) = h;
            *reinterpret_cast<uint32_t*>(&ol[(long)(row0 + 8) * N + colBase + cl]) = l;
        } else {
            *reinterpret_cast<float2*>(&of[(long)row0 * N + colBase + cl]) = make_float2(v0, v1);
            *reinterpret_cast<float2*>(&of[(long)(row0 + 8) * N + colBase + cl]) = make_float2(v2, v3);
        }
    }
}

// ---------------------------------------------------------------------------
// final dense [4096,128]@[128,1] + sigmoid
// ---------------------------------------------------------------------------
__global__ void final_kernel(const float* __restrict__ Wout,
                             const float* __restrict__ bout,
                             float* __restrict__ out)
{
    const int warp = (blockIdx.x * blockDim.x + threadIdx.x) >> 5;
    const int lane = threadIdx.x & 31;
    if (warp >= BATCH) return;
    const float* h = &g_h2[warp * 128];
    float acc = h[lane]      * Wout[lane]
              + h[lane + 32] * Wout[lane + 32]
              + h[lane + 64] * Wout[lane + 64]
              + h[lane + 96] * Wout[lane + 96];
    #pragma unroll
    for (int off = 16; off > 0; off >>= 1)
        acc += __shfl_down_sync(0xffffffffu, acc, off);
    if (lane == 0) {
        float z = acc + bout[0];
        out[warp] = 1.f / (1.f + expf(-z));
    }
}

// ---------------------------------------------------------------------------
extern "C" void kernel_launch(void* const* d_in, const int* in_sizes, int n_in,
                              void* d_out, int out_size)
{
    const float* fv    = (const float*)d_in[0];
    const int*   idx   = (const int*)  d_in[1];
    const float* emb   = (const float*)d_in[2];
    const float* LS    = (const float*)d_in[3];
    const float* theta = (const float*)d_in[4];
    const float* quad  = (const float*)d_in[5];
    const float* W0  = (const float*)d_in[6];
    const float* b0  = (const float*)d_in[7];
    const float* gm0 = (const float*)d_in[8];
    const float* be0 = (const float*)d_in[9];
    const float* m0  = (const float*)d_in[10];
    const float* v0  = (const float*)d_in[11];
    const float* W1  = (const float*)d_in[12];
    const float* b1  = (const float*)d_in[13];
    const float* gm1 = (const float*)d_in[14];
    const float* be1 = (const float*)d_in[15];
    const float* m1  = (const float*)d_in[16];
    const float* v1  = (const float*)d_in[17];
    const float* W2  = (const float*)d_in[18];
    const float* b2  = (const float*)d_in[19];
    const float* gm2 = (const float*)d_in[20];
    const float* be2 = (const float*)d_in[21];
    const float* m2  = (const float*)d_in[22];
    const float* v2  = (const float*)d_in[23];
    const float* Wout = (const float*)d_in[24];
    const float* bout = (const float*)d_in[25];
    float* out = (float*)d_out;

    float *p_x, *p_h2;
    __nv_bfloat16 *p_h0h, *p_h0l, *p_h1h, *p_h1l;
    __nv_bfloat16 *p_w0h, *p_w0l, *p_w1h, *p_w1l, *p_w2h, *p_w2l;
    cudaGetSymbolAddress((void**)&p_x,   g_x);
    cudaGetSymbolAddress((void**)&p_h0h, g_h0h);
    cudaGetSymbolAddress((void**)&p_h0l, g_h0l);
    cudaGetSymbolAddress((void**)&p_h1h, g_h1h);
    cudaGetSymbolAddress((void**)&p_h1l, g_h1l);
    cudaGetSymbolAddress((void**)&p_h2,  g_h2);
    cudaGetSymbolAddress((void**)&p_w0h, g_w0h);
    cudaGetSymbolAddress((void**)&p_w0l, g_w0l);
    cudaGetSymbolAddress((void**)&p_w1h, g_w1h);
    cudaGetSymbolAddress((void**)&p_w1l, g_w1l);
    cudaGetSymbolAddress((void**)&p_w2h, g_w2h);
    cudaGetSymbolAddress((void**)&p_w2l, g_w2l);

    const int SMEM_LZOP  = 2 * BUF64;                              // 110592 -> 2/SM
    const int SMEM_MLP8  = 2 * (18432 + 2 * 64 * PITCH) + 1024;    //  74752 -> 3/SM
    const int SMEM_MLP4  = 2 * (18432 + 2 * 32 * PITCH) + 1024;    //  56320 -> 4/SM
    cudaFuncSetAttribute(lzop_mma,       cudaFuncAttributeMaxDynamicSharedMemorySize, SMEM_LZOP);
    cudaFuncSetAttribute(mlp_mma<8,1,1>, cudaFuncAttributeMaxDynamicSharedMemorySize, SMEM_MLP8);
    cudaFuncSetAttribute(mlp_mma<8,1,0>, cudaFuncAttributeMaxDynamicSharedMemorySize, SMEM_MLP8);
    cudaFuncSetAttribute(mlp_mma<4,0,0>, cudaFuncAttributeMaxDynamicSharedMemorySize, SMEM_MLP4);

    // 1) fused gather + operand prep
    prep_gather<<<5576, 256>>>(fv, idx, emb, theta, W0, W1, W2, LS, quad);
    // 2) merged l_z + l_p_out (1280 blocks, lz first)
    lzop_mma<<<1280, 256, SMEM_LZOP>>>(fv, idx, emb);
    // 3) MLP (BM=64, 128 threads; mlp0 at NT=8 for occupancy)
    mlp_mma<8,1,1><<<dim3(8, 64), 128, SMEM_MLP8>>>(p_x, nullptr, nullptr,
        p_w0h, p_w0l, p_h0h, p_h0l, nullptr, 192, 512, b0, gm0, be0, m0, v0);
    mlp_mma<8,1,0><<<dim3(4, 64), 128, SMEM_MLP8>>>(nullptr, p_h0h, p_h0l,
        p_w1h, p_w1l, p_h1h, p_h1l, nullptr, 512, 256, b1, gm1, be1, m1, v1);
    mlp_mma<4,0,0><<<dim3(4, 64), 128, SMEM_MLP4>>>(nullptr, p_h1h, p_h1l,
        p_w2h, p_w2l, nullptr, nullptr, p_h2, 256, 128, b2, gm2, be2, m2, v2);
    // 4) output + sigmoid
    final_kernel<<<BATCH * 32 / 256, 256>>>(Wout, bout, out);
}